// round 8
// baseline (speedup 1.0000x reference)
#include <cuda_runtime.h>
#include <cuda_bf16.h>
#include <cstdint>

#define N_NODE 50000
#define N_EDGE 800000
#define HID 128
#define ZD 128
#define ED 64
#define N_ROWS (N_NODE * 4)
#define NT 12500                 // 64-edge tiles

// ---------------- scratch (device globals: no allocation allowed) ----------------
__device__ float g_AB[N_NODE * 256];
__device__ float g_E2[N_ROWS * HID];
__device__ float g_W1T[128 * 256];
__device__ float g_We1T[64 * 128];
__device__ float g_We2T[128 * 128];
__device__ __nv_bfloat16 g_W2hi[128 * 128];   // zW2 [n][k] bf16 hi
__device__ __nv_bfloat16 g_W2lo[128 * 128];   // zW2 [n][k] bf16 lo

__device__ __forceinline__ float silu_f(float x) {
    return x * __fdividef(1.0f, 1.0f + __expf(-x));
}
__device__ __forceinline__ uint32_t smem_u32(const void* p) {
    uint32_t a;
    asm("{ .reg .u64 t; cvta.to.shared.u64 t, %1; cvt.u32.u64 %0, t; }" : "=r"(a) : "l"(p));
    return a;
}
__device__ __forceinline__ void ldsm_x4(uint32_t* r, uint32_t addr) {
    asm volatile("ldmatrix.sync.aligned.m8n8.x4.shared.b16 {%0,%1,%2,%3}, [%4];"
        : "=r"(r[0]), "=r"(r[1]), "=r"(r[2]), "=r"(r[3]) : "r"(addr));
}
__device__ __forceinline__ void mma_16816(float* d, const uint32_t* a, uint32_t b0, uint32_t b1) {
    asm volatile(
        "mma.sync.aligned.m16n8k16.row.col.f32.bf16.bf16.f32 "
        "{%0,%1,%2,%3}, {%4,%5,%6,%7}, {%8,%9}, {%0,%1,%2,%3};"
        : "+f"(d[0]), "+f"(d[1]), "+f"(d[2]), "+f"(d[3])
        : "r"(a[0]), "r"(a[1]), "r"(a[2]), "r"(a[3]), "r"(b0), "r"(b1));
}

// ---------------- kernel 0: weight transposes + bf16 split ----------------
__global__ void prep_kernel(const float* __restrict__ zW1,
                            const float* __restrict__ zW2,
                            const float* __restrict__ eW1,
                            const float* __restrict__ eW2) {
    int i = blockIdx.x * blockDim.x + threadIdx.x;
    if (i < 32768) {
        int k = i >> 8, c = i & 255;
        g_W1T[i] = (c < 128) ? zW1[c * 256 + k] : zW1[(c - 128) * 256 + 128 + k];
    } else if (i < 40960) {
        int q = i - 32768; int k = q >> 7, n = q & 127;
        g_We1T[q] = eW1[n * 64 + k];
    } else if (i < 57344) {
        int q = i - 40960; int k = q >> 7, n = q & 127;
        g_We2T[q] = eW2[n * 128 + k];
    } else if (i < 73728) {
        int q = i - 57344;
        float v = zW2[q];
        __nv_bfloat16 h = __float2bfloat16(v);
        g_W2hi[q] = h;
        g_W2lo[q] = __float2bfloat16(v - __bfloat162float(h));
    }
}

// ---------------- kernel 1: per-node A|B = silu(z) @ W1eff^T (FFMA, proven) ----------------
__global__ __launch_bounds__(256, 2)
void nodeAB_kernel(const float* __restrict__ z_embed) {
    extern __shared__ float sm[];
    float* sP = sm;
    float* sW = sm + 16384;
    const int tid = threadIdx.x;
    const int m0 = blockIdx.x * 128;
    const int half = blockIdx.y;

    #pragma unroll
    for (int it = 0; it < 16; ++it) {
        int m = it * 8 + (tid >> 5);
        int k4 = (tid & 31) * 4;
        int node = m0 + m;
        float4 v = make_float4(0.f, 0.f, 0.f, 0.f);
        if (node < N_NODE) v = *reinterpret_cast<const float4*>(&z_embed[node * ZD + k4]);
        v.x = silu_f(v.x); v.y = silu_f(v.y); v.z = silu_f(v.z); v.w = silu_f(v.w);
        *reinterpret_cast<float4*>(&sP[m * 128 + k4]) = v;
    }

    const int ty = tid >> 4, tx = tid & 15;
    const int mB = ty * 8, nB = tx * 8;
    float acc[8][8];
    #pragma unroll
    for (int r = 0; r < 8; ++r)
        #pragma unroll
        for (int c = 0; c < 8; ++c) acc[r][c] = 0.f;

    for (int c64 = 0; c64 < 2; ++c64) {
        if (c64) __syncthreads();
        #pragma unroll
        for (int it = 0; it < 8; ++it) {
            int kr = it * 8 + (tid >> 5);
            int n4 = (tid & 31) * 4;
            float4 w = *reinterpret_cast<const float4*>(
                &g_W1T[(c64 * 64 + kr) * 256 + half * 128 + n4]);
            *reinterpret_cast<float4*>(&sW[kr * 132 + n4]) = w;
        }
        __syncthreads();
        #pragma unroll 4
        for (int k = 0; k < 64; ++k) {
            float a[8], b[8];
            #pragma unroll
            for (int r = 0; r < 8; ++r) a[r] = sP[(mB + r) * 128 + c64 * 64 + k];
            float4 b0 = *reinterpret_cast<const float4*>(&sW[k * 132 + nB]);
            float4 b1 = *reinterpret_cast<const float4*>(&sW[k * 132 + nB + 4]);
            b[0]=b0.x; b[1]=b0.y; b[2]=b0.z; b[3]=b0.w;
            b[4]=b1.x; b[5]=b1.y; b[6]=b1.z; b[7]=b1.w;
            #pragma unroll
            for (int r = 0; r < 8; ++r)
                #pragma unroll
                for (int c = 0; c < 8; ++c) acc[r][c] = fmaf(a[r], b[c], acc[r][c]);
        }
    }

    #pragma unroll
    for (int r = 0; r < 8; ++r) {
        int node = m0 + mB + r;
        if (node < N_NODE) {
            #pragma unroll
            for (int c = 0; c < 8; c += 4) {
                float4 o = make_float4(acc[r][c], acc[r][c+1], acc[r][c+2], acc[r][c+3]);
                *reinterpret_cast<float4*>(&g_AB[node * 256 + half * 128 + nB + c]) = o;
            }
        }
    }
}

// ---------------- kernel 2: per-(node,orb) e-branch (FFMA, proven) ----------------
__global__ __launch_bounds__(256, 1)
void nodeE_kernel(const float* __restrict__ e_embed) {
    extern __shared__ float sm[];
    float* sX  = sm;
    float* sW1 = sm + 8192;
    float* sH  = sm + 16640;
    float* sW2 = sm + 33024;
    const int tid = threadIdx.x;
    const int r0 = blockIdx.x * 128;

    #pragma unroll
    for (int it = 0; it < 8; ++it) {
        int m = it * 16 + (tid >> 4);
        int k4 = (tid & 15) * 4;
        int row = r0 + m;
        float4 v = make_float4(0.f, 0.f, 0.f, 0.f);
        if (row < N_ROWS) v = *reinterpret_cast<const float4*>(&e_embed[row * ED + k4]);
        v.x = silu_f(v.x); v.y = silu_f(v.y); v.z = silu_f(v.z); v.w = silu_f(v.w);
        *reinterpret_cast<float4*>(&sX[m * 64 + k4]) = v;
    }
    #pragma unroll
    for (int it = 0; it < 8; ++it) {
        int kr = it * 8 + (tid >> 5);
        int n4 = (tid & 31) * 4;
        float4 w = *reinterpret_cast<const float4*>(&g_We1T[kr * 128 + n4]);
        *reinterpret_cast<float4*>(&sW1[kr * 132 + n4]) = w;
    }
    #pragma unroll
    for (int it = 0; it < 16; ++it) {
        int kr = it * 8 + (tid >> 5);
        int n4 = (tid & 31) * 4;
        float4 w = *reinterpret_cast<const float4*>(&g_We2T[kr * 128 + n4]);
        *reinterpret_cast<float4*>(&sW2[kr * 132 + n4]) = w;
    }
    __syncthreads();

    const int ty = tid >> 4, tx = tid & 15;
    const int mB = ty * 8, nB = tx * 8;
    float acc[8][8];
    #pragma unroll
    for (int r = 0; r < 8; ++r)
        #pragma unroll
        for (int c = 0; c < 8; ++c) acc[r][c] = 0.f;

    #pragma unroll 4
    for (int k = 0; k < 64; ++k) {
        float a[8], b[8];
        #pragma unroll
        for (int r = 0; r < 8; ++r) a[r] = sX[(mB + r) * 64 + k];
        float4 b0 = *reinterpret_cast<const float4*>(&sW1[k * 132 + nB]);
        float4 b1 = *reinterpret_cast<const float4*>(&sW1[k * 132 + nB + 4]);
        b[0]=b0.x; b[1]=b0.y; b[2]=b0.z; b[3]=b0.w;
        b[4]=b1.x; b[5]=b1.y; b[6]=b1.z; b[7]=b1.w;
        #pragma unroll
        for (int r = 0; r < 8; ++r)
            #pragma unroll
            for (int c = 0; c < 8; ++c) acc[r][c] = fmaf(a[r], b[c], acc[r][c]);
    }

    #pragma unroll
    for (int r = 0; r < 8; ++r) {
        #pragma unroll
        for (int c = 0; c < 8; c += 4) {
            float4 h;
            h.x = silu_f(acc[r][c]);   h.y = silu_f(acc[r][c+1]);
            h.z = silu_f(acc[r][c+2]); h.w = silu_f(acc[r][c+3]);
            *reinterpret_cast<float4*>(&sH[(mB + r) * 128 + nB + c]) = h;
        }
    }
    __syncthreads();

    float acc2[8][8];
    #pragma unroll
    for (int r = 0; r < 8; ++r)
        #pragma unroll
        for (int c = 0; c < 8; ++c) acc2[r][c] = 0.f;

    #pragma unroll 4
    for (int k = 0; k < 128; ++k) {
        float a[8], b[8];
        #pragma unroll
        for (int r = 0; r < 8; ++r) a[r] = sH[(mB + r) * 128 + k];
        float4 b0 = *reinterpret_cast<const float4*>(&sW2[k * 132 + nB]);
        float4 b1 = *reinterpret_cast<const float4*>(&sW2[k * 132 + nB + 4]);
        b[0]=b0.x; b[1]=b0.y; b[2]=b0.z; b[3]=b0.w;
        b[4]=b1.x; b[5]=b1.y; b[6]=b1.z; b[7]=b1.w;
        #pragma unroll
        for (int r = 0; r < 8; ++r)
            #pragma unroll
            for (int c = 0; c < 8; ++c) acc2[r][c] = fmaf(a[r], b[c], acc2[r][c]);
    }

    #pragma unroll
    for (int r = 0; r < 8; ++r) {
        int row = r0 + mB + r;
        if (row < N_ROWS) {
            #pragma unroll
            for (int c = 0; c < 8; c += 4) {
                float4 o = make_float4(acc2[r][c], acc2[r][c+1], acc2[r][c+2], acc2[r][c+3]);
                *reinterpret_cast<float4*>(&g_E2[row * 128 + nB + c]) = o;
            }
        }
    }
}

// ---------------- kernel 3: persistent HMMA edge kernel, B-fragments in registers ----------------
// smem: A tile (hi 16K + lo 16K) @0; SG 64x132 f32 @32768; zb2 @66560; sJ[2][64] @67072
#define OFF_A   0
#define OFF_SG  32768
#define OFF_B2  66560
#define OFF_J   67072
#define SMEM_EDGE 67584

__global__ __launch_bounds__(256, 2)
void edge_mma_kernel(const int* __restrict__ idx_i, const int* __restrict__ idx_j,
                     const float* __restrict__ zb1, const float* __restrict__ zb2,
                     float* __restrict__ out) {
    extern __shared__ char smc[];
    const uint32_t sb = smem_u32(smc);
    float* sG  = reinterpret_cast<float*>(smc + OFF_SG);
    float* sB2 = reinterpret_cast<float*>(smc + OFF_B2);
    int*   sJ  = reinterpret_cast<int*>(smc + OFF_J);
    const int tid = threadIdx.x;
    const int lane = tid & 31;
    const int wid = tid >> 5;              // 0..7, n-slab of 16

    if (tid < 128) sB2[tid] = zb2[tid];

    // B-hi fragments resident in registers (mma.m16n8k16 col-B layout:
    // lane l: b0 = W[n = slab + (l>>2)][k = kk*16 + 2*(l&3) + {0,1}], b1 at k+8)
    uint32_t bhi[8][2][2];
    {
        const char* wb = reinterpret_cast<const char*>(g_W2hi);
        #pragma unroll
        for (int kk = 0; kk < 8; ++kk)
            #pragma unroll
            for (int ni = 0; ni < 2; ++ni) {
                uint32_t base = (uint32_t)((wid * 16 + ni * 8 + (lane >> 2)) * 256 + kk * 32 + 4 * (lane & 3));
                bhi[kk][ni][0] = *reinterpret_cast<const uint32_t*>(wb + base);
                bhi[kk][ni][1] = *reinterpret_cast<const uint32_t*>(wb + base + 16);
            }
    }
    const char* wlo = reinterpret_cast<const char*>(g_W2lo);

    const int bm  = tid >> 2;              // build row 0..63
    const int bk0 = (tid & 3) * 32;        // build k slab
    const int aRowL = lane & 15;
    const int aSel  = lane >> 4;
    const int gr  = lane >> 2;
    const int gcol = wid * 16 + 2 * (lane & 3);
    const int eh  = lane * 4;

    int par = 0;
    for (int t = blockIdx.x; t < NT; t += gridDim.x, par ^= 1) {
        const int e0 = t * 64;
        if (tid < 64) sJ[par * 64 + tid] = __ldg(&idx_j[e0 + tid]);

        // ---- build s tile (bf16 hi/lo, swizzled), two 4-chunk halves ----
        {
            int e = e0 + bm;
            int i = __ldg(&idx_i[e]);
            int j = __ldg(&idx_j[e]);
            #pragma unroll
            for (int hhalf = 0; hhalf < 2; ++hhalf) {
                float4 ga[4], gb[4];
                #pragma unroll
                for (int q = 0; q < 4; ++q) {
                    int k = bk0 + hhalf * 16 + q * 4;
                    ga[q] = __ldg(reinterpret_cast<const float4*>(&g_AB[i * 256 + k]));
                    gb[q] = __ldg(reinterpret_cast<const float4*>(&g_AB[j * 256 + 128 + k]));
                }
                #pragma unroll
                for (int q = 0; q < 4; ++q) {
                    int k = bk0 + hhalf * 16 + q * 4;
                    float4 bias = __ldg(reinterpret_cast<const float4*>(&zb1[k]));
                    float s0 = silu_f(ga[q].x + gb[q].x + bias.x);
                    float s1 = silu_f(ga[q].y + gb[q].y + bias.y);
                    float s2 = silu_f(ga[q].z + gb[q].z + bias.z);
                    float s3 = silu_f(ga[q].w + gb[q].w + bias.w);
                    __nv_bfloat16 h0 = __float2bfloat16(s0), h1 = __float2bfloat16(s1);
                    __nv_bfloat16 h2 = __float2bfloat16(s2), h3 = __float2bfloat16(s3);
                    __nv_bfloat16 l0 = __float2bfloat16(s0 - __bfloat162float(h0));
                    __nv_bfloat16 l1 = __float2bfloat16(s1 - __bfloat162float(h1));
                    __nv_bfloat16 l2 = __float2bfloat16(s2 - __bfloat162float(h2));
                    __nv_bfloat16 l3 = __float2bfloat16(s3 - __bfloat162float(h3));
                    uint2 hp, lp;
                    hp.x = (uint32_t)__bfloat16_as_ushort(h0) | ((uint32_t)__bfloat16_as_ushort(h1) << 16);
                    hp.y = (uint32_t)__bfloat16_as_ushort(h2) | ((uint32_t)__bfloat16_as_ushort(h3) << 16);
                    lp.x = (uint32_t)__bfloat16_as_ushort(l0) | ((uint32_t)__bfloat16_as_ushort(l1) << 16);
                    lp.y = (uint32_t)__bfloat16_as_ushort(l2) | ((uint32_t)__bfloat16_as_ushort(l3) << 16);
                    int c = k >> 3;
                    uint32_t d = (uint32_t)(bm * 256 + ((c ^ (bm & 7)) << 4) + ((k >> 2) & 1) * 8);
                    *reinterpret_cast<uint2*>(smc + OFF_A + d) = hp;
                    *reinterpret_cast<uint2*>(smc + OFF_A + 16384 + d) = lp;
                }
            }
        }
        __syncthreads();

        // ---- MMA: warp = full M(64) x 16-n slab; 3 passes x 8 kk ----
        float acc[4][2][4];
        #pragma unroll
        for (int mi = 0; mi < 4; ++mi)
            #pragma unroll
            for (int ni = 0; ni < 2; ++ni)
                #pragma unroll
                for (int q = 0; q < 4; ++q) acc[mi][ni][q] = 0.f;

        #pragma unroll
        for (int p = 0; p < 3; ++p) {
            const uint32_t aB = sb + OFF_A + ((p == 2) ? 16384u : 0u);
            #pragma unroll
            for (int kk = 0; kk < 8; ++kk) {
                const int c0 = kk * 2;
                uint32_t af[4][4];
                #pragma unroll
                for (int mi = 0; mi < 4; ++mi) {
                    int row = mi * 16 + aRowL;
                    ldsm_x4(af[mi], aB + row * 256 + (((c0 + aSel) ^ (row & 7)) << 4));
                }
                uint32_t b0[2], b1[2];
                if (p == 1) {
                    #pragma unroll
                    for (int ni = 0; ni < 2; ++ni) {
                        uint32_t base = (uint32_t)((wid * 16 + ni * 8 + (lane >> 2)) * 256 + kk * 32 + 4 * (lane & 3));
                        b0[ni] = *reinterpret_cast<const uint32_t*>(wlo + base);
                        b1[ni] = *reinterpret_cast<const uint32_t*>(wlo + base + 16);
                    }
                } else {
                    #pragma unroll
                    for (int ni = 0; ni < 2; ++ni) { b0[ni] = bhi[kk][ni][0]; b1[ni] = bhi[kk][ni][1]; }
                }
                #pragma unroll
                for (int mi = 0; mi < 4; ++mi) {
                    mma_16816(acc[mi][0], af[mi], b0[0], b1[0]);
                    mma_16816(acc[mi][1], af[mi], b0[1], b1[1]);
                }
            }
        }

        // ---- g = 1 + z2 + zb2 -> sG [64][132] ----
        #pragma unroll
        for (int mi = 0; mi < 4; ++mi) {
            #pragma unroll
            for (int ni = 0; ni < 2; ++ni) {
                int col = gcol + ni * 8;
                int r0 = mi * 16 + gr;
                float2 v0, v1;
                v0.x = 1.f + acc[mi][ni][0] + sB2[col];
                v0.y = 1.f + acc[mi][ni][1] + sB2[col + 1];
                v1.x = 1.f + acc[mi][ni][2] + sB2[col];
                v1.y = 1.f + acc[mi][ni][3] + sB2[col + 1];
                *reinterpret_cast<float2*>(&sG[r0 * 132 + col]) = v0;
                *reinterpret_cast<float2*>(&sG[(r0 + 8) * 132 + col]) = v1;
            }
        }
        __syncthreads();

        // ---- epilogue: out[e, orb, h] = E2[j, orb, h] * g[e, h] ----
        #pragma unroll 8
        for (int it = 0; it < 32; ++it) {
            int row = it * 8 + wid;          // (m, orb) flat
            int m = row >> 2, orb = row & 3;
            int j = sJ[par * 64 + m];
            float4 ev = __ldg(reinterpret_cast<const float4*>(&g_E2[(j * 4 + orb) * 128 + eh]));
            float4 g  = *reinterpret_cast<const float4*>(&sG[m * 132 + eh]);
            float4 o;
            o.x = ev.x * g.x; o.y = ev.y * g.y; o.z = ev.z * g.z; o.w = ev.w * g.w;
            size_t off = ((size_t)(e0 + m) * 4 + orb) * 128 + eh;
            __stcs(reinterpret_cast<float4*>(&out[off]), o);
        }
    }
}

// ---------------- launch ----------------
extern "C" void kernel_launch(void* const* d_in, const int* in_sizes, int n_in,
                              void* d_out, int out_size) {
    const float* z_embed = (const float*)d_in[0];
    const float* e_embed = (const float*)d_in[1];
    const int*   idx_i   = (const int*)d_in[2];
    const int*   idx_j   = (const int*)d_in[3];
    const float* zW1     = (const float*)d_in[4];
    const float* zb1     = (const float*)d_in[5];
    const float* zW2     = (const float*)d_in[6];
    const float* zb2     = (const float*)d_in[7];
    const float* eW1     = (const float*)d_in[8];
    const float* eW2     = (const float*)d_in[9];
    float* out = (float*)d_out;

    const int SMEM1 = (16384 + 64 * 132) * 4;
    const int SMEM2 = (8192 + 64 * 132 + 16384 + 128 * 132) * 4;
    cudaFuncSetAttribute(nodeAB_kernel, cudaFuncAttributeMaxDynamicSharedMemorySize, SMEM1);
    cudaFuncSetAttribute(nodeE_kernel,  cudaFuncAttributeMaxDynamicSharedMemorySize, SMEM2);
    cudaFuncSetAttribute(edge_mma_kernel, cudaFuncAttributeMaxDynamicSharedMemorySize, SMEM_EDGE);

    prep_kernel<<<288, 256>>>(zW1, zW2, eW1, eW2);
    nodeAB_kernel<<<dim3(391, 2), 256, SMEM1>>>(z_embed);
    nodeE_kernel<<<1563, 256, SMEM2>>>(e_embed);
    edge_mma_kernel<<<296, 256, SMEM_EDGE>>>(idx_i, idx_j, zb1, zb2, out);
}

// round 10
// speedup vs baseline: 1.2760x; 1.2760x over previous
#include <cuda_runtime.h>

#define N_NODE 50000
#define N_EDGE 800000
#define HID 128
#define ZD 128
#define ED 64
#define N_ROWS (N_NODE * 4)

// ---------------- scratch (device globals: no allocation allowed) ----------------
__device__ float g_AB[N_NODE * 256];         // [node][0:128]=A, [128:256]=B
__device__ float g_E2[N_ROWS * HID];         // e-branch output per (node,orb)
__device__ float g_W1T[128 * 256];           // Weff[k][c]
__device__ float g_W2T[128 * 128];           // zW2[n][k] -> [k][n]
__device__ float g_We1T[64 * 128];           // eW1[n][k] -> [k][n]
__device__ float g_We2T[128 * 128];          // eW2[n][k] -> [k][n]

__device__ __forceinline__ float silu_f(float x) {
    return x * __fdividef(1.0f, 1.0f + __expf(-x));
}

// ---------------- kernel 0: weight transposes ----------------
__global__ void prep_kernel(const float* __restrict__ zW1,
                            const float* __restrict__ zW2,
                            const float* __restrict__ eW1,
                            const float* __restrict__ eW2) {
    int i = blockIdx.x * blockDim.x + threadIdx.x;
    if (i < 32768) {                       // g_W1T: 128 k x 256 c
        int k = i >> 8, c = i & 255;
        g_W1T[i] = (c < 128) ? zW1[c * 256 + k] : zW1[(c - 128) * 256 + 128 + k];
    } else if (i < 49152) {                // g_W2T
        int q = i - 32768; int k = q >> 7, n = q & 127;
        g_W2T[q] = zW2[n * 128 + k];
    } else if (i < 57344) {                // g_We1T (64 k x 128 n)
        int q = i - 49152; int k = q >> 7, n = q & 127;
        g_We1T[q] = eW1[n * 64 + k];
    } else if (i < 73728) {                // g_We2T
        int q = i - 57344; int k = q >> 7, n = q & 127;
        g_We2T[q] = eW2[n * 128 + k];
    }
}

// 4-k micro-kernel: KA = k offset in activation tile, KW = k offset in weight tile
#define GEMM_STEP4(SPTR, SLD, KA, SW, KW, ACC)                                  \
    {                                                                           \
        float4 a4[8];                                                           \
        _Pragma("unroll")                                                       \
        for (int r = 0; r < 8; ++r)                                             \
            a4[r] = *reinterpret_cast<const float4*>(&(SPTR)[(mB + r) * (SLD) + (KA)]); \
        _Pragma("unroll")                                                       \
        for (int kq = 0; kq < 4; ++kq) {                                        \
            float4 b0 = *reinterpret_cast<const float4*>(&(SW)[((KW) + kq) * 132 + nB]);     \
            float4 b1 = *reinterpret_cast<const float4*>(&(SW)[((KW) + kq) * 132 + nB + 4]); \
            _Pragma("unroll")                                                   \
            for (int r = 0; r < 8; ++r) {                                       \
                float av = (kq == 0) ? a4[r].x : (kq == 1) ? a4[r].y            \
                          : (kq == 2) ? a4[r].z : a4[r].w;                      \
                ACC[r][0] = fmaf(av, b0.x, ACC[r][0]);                          \
                ACC[r][1] = fmaf(av, b0.y, ACC[r][1]);                          \
                ACC[r][2] = fmaf(av, b0.z, ACC[r][2]);                          \
                ACC[r][3] = fmaf(av, b0.w, ACC[r][3]);                          \
                ACC[r][4] = fmaf(av, b1.x, ACC[r][4]);                          \
                ACC[r][5] = fmaf(av, b1.y, ACC[r][5]);                          \
                ACC[r][6] = fmaf(av, b1.z, ACC[r][6]);                          \
                ACC[r][7] = fmaf(av, b1.w, ACC[r][7]);                          \
            }                                                                   \
        }                                                                       \
    }

// ---------------- kernel 1: per-node A|B = silu(z) @ W1eff^T ----------------
__global__ __launch_bounds__(256, 2)
void nodeAB_kernel(const float* __restrict__ z_embed) {
    extern __shared__ float sm[];
    float* sP = sm;            // [128][128]
    float* sW = sm + 16384;    // [64][132]
    const int tid = threadIdx.x;
    const int m0 = blockIdx.x * 128;
    const int half = blockIdx.y;

    #pragma unroll
    for (int it = 0; it < 16; ++it) {
        int m = it * 8 + (tid >> 5);
        int k4 = (tid & 31) * 4;
        int node = m0 + m;
        float4 v = make_float4(0.f, 0.f, 0.f, 0.f);
        if (node < N_NODE) v = *reinterpret_cast<const float4*>(&z_embed[node * ZD + k4]);
        v.x = silu_f(v.x); v.y = silu_f(v.y); v.z = silu_f(v.z); v.w = silu_f(v.w);
        *reinterpret_cast<float4*>(&sP[m * 128 + k4]) = v;
    }

    const int ty = tid >> 4, tx = tid & 15;
    const int mB = ty * 8, nB = tx * 8;
    float acc[8][8];
    #pragma unroll
    for (int r = 0; r < 8; ++r)
        #pragma unroll
        for (int c = 0; c < 8; ++c) acc[r][c] = 0.f;

    for (int c64 = 0; c64 < 2; ++c64) {
        if (c64) __syncthreads();
        #pragma unroll
        for (int it = 0; it < 8; ++it) {
            int kr = it * 8 + (tid >> 5);
            int n4 = (tid & 31) * 4;
            float4 w = *reinterpret_cast<const float4*>(
                &g_W1T[(c64 * 64 + kr) * 256 + half * 128 + n4]);
            *reinterpret_cast<float4*>(&sW[kr * 132 + n4]) = w;
        }
        __syncthreads();
        for (int k = 0; k < 64; k += 4)
            GEMM_STEP4(sP, 128, c64 * 64 + k, sW, k, acc)
    }

    #pragma unroll
    for (int r = 0; r < 8; ++r) {
        int node = m0 + mB + r;
        if (node < N_NODE) {
            #pragma unroll
            for (int c = 0; c < 8; c += 4) {
                float4 o = make_float4(acc[r][c], acc[r][c+1], acc[r][c+2], acc[r][c+3]);
                *reinterpret_cast<float4*>(&g_AB[node * 256 + half * 128 + nB + c]) = o;
            }
        }
    }
}

// ---------------- kernel 2: per-(node,orb) e-branch, fused 2 layers ----------------
__global__ __launch_bounds__(256, 1)
void nodeE_kernel(const float* __restrict__ e_embed) {
    extern __shared__ float sm[];
    float* sX  = sm;            // [128][64]
    float* sW1 = sm + 8192;     // [64][132]
    float* sH  = sm + 16640;    // [128][128]
    float* sW2 = sm + 33024;    // [128][132]
    const int tid = threadIdx.x;
    const int r0 = blockIdx.x * 128;

    #pragma unroll
    for (int it = 0; it < 8; ++it) {
        int m = it * 16 + (tid >> 4);
        int k4 = (tid & 15) * 4;
        int row = r0 + m;
        float4 v = make_float4(0.f, 0.f, 0.f, 0.f);
        if (row < N_ROWS) v = *reinterpret_cast<const float4*>(&e_embed[row * ED + k4]);
        v.x = silu_f(v.x); v.y = silu_f(v.y); v.z = silu_f(v.z); v.w = silu_f(v.w);
        *reinterpret_cast<float4*>(&sX[m * 64 + k4]) = v;
    }
    #pragma unroll
    for (int it = 0; it < 8; ++it) {
        int kr = it * 8 + (tid >> 5);
        int n4 = (tid & 31) * 4;
        float4 w = *reinterpret_cast<const float4*>(&g_We1T[kr * 128 + n4]);
        *reinterpret_cast<float4*>(&sW1[kr * 132 + n4]) = w;
    }
    #pragma unroll
    for (int it = 0; it < 16; ++it) {
        int kr = it * 8 + (tid >> 5);
        int n4 = (tid & 31) * 4;
        float4 w = *reinterpret_cast<const float4*>(&g_We2T[kr * 128 + n4]);
        *reinterpret_cast<float4*>(&sW2[kr * 132 + n4]) = w;
    }
    __syncthreads();

    const int ty = tid >> 4, tx = tid & 15;
    const int mB = ty * 8, nB = tx * 8;
    float acc[8][8];
    #pragma unroll
    for (int r = 0; r < 8; ++r)
        #pragma unroll
        for (int c = 0; c < 8; ++c) acc[r][c] = 0.f;

    for (int k = 0; k < 64; k += 4)                 // layer 1
        GEMM_STEP4(sX, 64, k, sW1, k, acc)

    #pragma unroll
    for (int r = 0; r < 8; ++r) {                   // sH = silu(layer1)
        #pragma unroll
        for (int c = 0; c < 8; c += 4) {
            float4 h;
            h.x = silu_f(acc[r][c]);   h.y = silu_f(acc[r][c+1]);
            h.z = silu_f(acc[r][c+2]); h.w = silu_f(acc[r][c+3]);
            *reinterpret_cast<float4*>(&sH[(mB + r) * 128 + nB + c]) = h;
        }
    }
    __syncthreads();

    float acc2[8][8];
    #pragma unroll
    for (int r = 0; r < 8; ++r)
        #pragma unroll
        for (int c = 0; c < 8; ++c) acc2[r][c] = 0.f;

    for (int k = 0; k < 128; k += 4)                // layer 2
        GEMM_STEP4(sH, 128, k, sW2, k, acc2)

    #pragma unroll
    for (int r = 0; r < 8; ++r) {
        int row = r0 + mB + r;
        if (row < N_ROWS) {
            #pragma unroll
            for (int c = 0; c < 8; c += 4) {
                float4 o = make_float4(acc2[r][c], acc2[r][c+1], acc2[r][c+2], acc2[r][c+3]);
                *reinterpret_cast<float4*>(&g_E2[row * 128 + nB + c]) = o;
            }
        }
    }
}

// ---------------- kernel 3: per-edge second layer + epilogue ----------------
__global__ __launch_bounds__(256, 2)
void edge_kernel(const int* __restrict__ idx_i, const int* __restrict__ idx_j,
                 const float* __restrict__ zb1, const float* __restrict__ zb2,
                 float* __restrict__ out) {
    extern __shared__ float sm[];
    float* sS  = sm;            // [128][128]  s tile; later reused as g
    float* sW  = sm + 16384;    // [64][132] -> ends 24832
    float* sB2 = sm + 24832;    // [128]
    int*   sJ  = reinterpret_cast<int*>(sm + 24960);  // [128] -> ends 25088
    const int tid = threadIdx.x;
    const int e0 = blockIdx.x * 128;

    if (tid < 128) {
        sB2[tid] = zb2[tid];
        sJ[tid] = idx_j[e0 + tid];
    }

    // build s tile
    #pragma unroll
    for (int it = 0; it < 16; ++it) {
        int m = it * 8 + (tid >> 5);
        int k4 = (tid & 31) * 4;
        int e = e0 + m;
        int i = __ldg(&idx_i[e]);
        int j = __ldg(&idx_j[e]);
        float4 a = *reinterpret_cast<const float4*>(&g_AB[i * 256 + k4]);
        float4 b = *reinterpret_cast<const float4*>(&g_AB[j * 256 + 128 + k4]);
        float4 bias = __ldg(reinterpret_cast<const float4*>(&zb1[k4]));
        float4 s;
        s.x = silu_f(a.x + b.x + bias.x);
        s.y = silu_f(a.y + b.y + bias.y);
        s.z = silu_f(a.z + b.z + bias.z);
        s.w = silu_f(a.w + b.w + bias.w);
        *reinterpret_cast<float4*>(&sS[m * 128 + k4]) = s;
    }

    const int ty = tid >> 4, tx = tid & 15;
    const int mB = ty * 8, nB = tx * 8;
    float acc[8][8];
    #pragma unroll
    for (int r = 0; r < 8; ++r)
        #pragma unroll
        for (int c = 0; c < 8; ++c) acc[r][c] = 0.f;

    for (int c64 = 0; c64 < 2; ++c64) {
        if (c64) __syncthreads();
        #pragma unroll
        for (int it = 0; it < 8; ++it) {
            int kr = it * 8 + (tid >> 5);
            int n4 = (tid & 31) * 4;
            float4 w = *reinterpret_cast<const float4*>(&g_W2T[(c64 * 64 + kr) * 128 + n4]);
            *reinterpret_cast<float4*>(&sW[kr * 132 + n4]) = w;
        }
        __syncthreads();
        for (int k = 0; k < 64; k += 4)
            GEMM_STEP4(sS, 128, c64 * 64 + k, sW, k, acc)
    }
    __syncthreads();    // done reading sS -> safe to overwrite with g

    // g = 1 + z2 + zb2
    #pragma unroll
    for (int r = 0; r < 8; ++r) {
        #pragma unroll
        for (int c = 0; c < 8; c += 4) {
            float4 g;
            g.x = 1.f + acc[r][c]   + sB2[nB + c];
            g.y = 1.f + acc[r][c+1] + sB2[nB + c + 1];
            g.z = 1.f + acc[r][c+2] + sB2[nB + c + 2];
            g.w = 1.f + acc[r][c+3] + sB2[nB + c + 3];
            *reinterpret_cast<float4*>(&sS[(mB + r) * 128 + nB + c]) = g;
        }
    }
    __syncthreads();

    // epilogue: out[e, orb, h] = E2[j, orb, h] * g[e, h]
    const int h = (tid & 31) * 4;
    const int orb = (tid >> 5) & 3;
    #pragma unroll 4
    for (int it = 0; it < 64; ++it) {
        int m = it * 2 + (tid >> 7);
        int j = sJ[m];
        float4 ev = *reinterpret_cast<const float4*>(&g_E2[(j * 4 + orb) * 128 + h]);
        float4 g  = *reinterpret_cast<const float4*>(&sS[m * 128 + h]);
        float4 o;
        o.x = ev.x * g.x; o.y = ev.y * g.y; o.z = ev.z * g.z; o.w = ev.w * g.w;
        size_t off = ((size_t)(e0 + m) * 4 + orb) * 128 + h;
        __stcs(reinterpret_cast<float4*>(&out[off]), o);
    }
}

// ---------------- launch ----------------
extern "C" void kernel_launch(void* const* d_in, const int* in_sizes, int n_in,
                              void* d_out, int out_size) {
    const float* z_embed = (const float*)d_in[0];
    const float* e_embed = (const float*)d_in[1];
    const int*   idx_i   = (const int*)d_in[2];
    const int*   idx_j   = (const int*)d_in[3];
    const float* zW1     = (const float*)d_in[4];
    const float* zb1     = (const float*)d_in[5];
    const float* zW2     = (const float*)d_in[6];
    const float* zb2     = (const float*)d_in[7];
    const float* eW1     = (const float*)d_in[8];
    const float* eW2     = (const float*)d_in[9];
    float* out = (float*)d_out;

    const int SMEM1 = (16384 + 64 * 132) * 4;                    //  99328 B
    const int SMEM2 = (8192 + 64 * 132 + 16384 + 128 * 132) * 4; // 199680 B
    const int SMEM3 = (16384 + 64 * 132 + 128 + 128) * 4;        // 100352 B
    cudaFuncSetAttribute(nodeAB_kernel, cudaFuncAttributeMaxDynamicSharedMemorySize, SMEM1);
    cudaFuncSetAttribute(nodeE_kernel,  cudaFuncAttributeMaxDynamicSharedMemorySize, SMEM2);
    cudaFuncSetAttribute(edge_kernel,   cudaFuncAttributeMaxDynamicSharedMemorySize, SMEM3);

    prep_kernel<<<288, 256>>>(zW1, zW2, eW1, eW2);
    nodeAB_kernel<<<dim3(391, 2), 256, SMEM1>>>(z_embed);
    nodeE_kernel<<<1563, 256, SMEM2>>>(e_embed);
    edge_kernel<<<6250, 256, SMEM3>>>(idx_i, idx_j, zb1, zb2, out);
}